// round 7
// baseline (speedup 1.0000x reference)
#include <cuda_runtime.h>

#define BATCH 4
#define NN1 512
#define NN2 512
#define DIM 256
#define MROWS (BATCH * NN1)   // 2048

// scratch (allocation-free rule: device globals), TRANSPOSED layout [d][b*n]
__device__ float g_xp_t[DIM * MROWS];   // (x @ Wx + b1)^T
__device__ float g_yp_t[DIM * MROWS];   // (y @ Wy)^T

// ---------------------------------------------------------------------------
// packed f32x2 helpers
// ---------------------------------------------------------------------------
__device__ __forceinline__ unsigned long long pk2(float lo, float hi) {
    unsigned long long r;
    asm("mov.b64 %0, {%1, %2};" : "=l"(r) : "f"(lo), "f"(hi));
    return r;
}
__device__ __forceinline__ void upk2(float& lo, float& hi, unsigned long long v) {
    asm("mov.b64 {%0, %1}, %2;" : "=f"(lo), "=f"(hi) : "l"(v));
}
__device__ __forceinline__ unsigned long long f2add(unsigned long long a, unsigned long long b) {
    unsigned long long r;
    asm("add.rn.f32x2 %0, %1, %2;" : "=l"(r) : "l"(a), "l"(b));
    return r;
}
__device__ __forceinline__ unsigned long long f2mul(unsigned long long a, unsigned long long b) {
    unsigned long long r;
    asm("mul.rn.f32x2 %0, %1, %2;" : "=l"(r) : "l"(a), "l"(b));
    return r;
}
__device__ __forceinline__ unsigned long long f2fma(unsigned long long a, unsigned long long b,
                                                    unsigned long long c) {
    unsigned long long r;
    asm("fma.rn.f32x2 %0, %1, %2, %3;" : "=l"(r) : "l"(a), "l"(b), "l"(c));
    return r;
}
__device__ __forceinline__ float tanhf_hw(float x) {
    float r;
    asm("tanh.approx.f32 %0, %1;" : "=f"(r) : "f"(x));
    return r;
}

// ---------------------------------------------------------------------------
// Kernel 1: projection GEMM, output TRANSPOSED.
//   z==0:  g_xp_t[e][m] = sum_k x[m][k] * W1[k][e]        + b1[e]
//   z==1:  g_yp_t[e][m] = sum_k y[m][k] * W1[(256+k)][e]
// ---------------------------------------------------------------------------
#define PBM 64
#define PBN 64
#define PBK 32

__global__ __launch_bounds__(256)
void proj_kernel(const float* __restrict__ x,
                 const float* __restrict__ y,
                 const float* __restrict__ W1,
                 const float* __restrict__ b1)
{
    __shared__ float As[PBK][68];   // [k][m]
    __shared__ float Bs[PBK][68];   // [k][e]

    const int which = blockIdx.z;
    const float* A = which ? y : x;
    float* C = which ? g_yp_t : g_xp_t;     // [DIM][MROWS]
    const float* W = W1 + (which ? DIM * DIM : 0);

    const int m0 = blockIdx.x * PBM;
    const int e0 = blockIdx.y * PBN;
    const int tid = threadIdx.x;
    const int tx = tid % 16;   // e group (4 wide)
    const int ty = tid / 16;   // m group (4 wide)

    float acc[4][4] = {};      // acc[i(m)][j(e)]

    for (int k0 = 0; k0 < DIM; k0 += PBK) {
        #pragma unroll
        for (int p = 0; p < 2; p++) {
            int r = tid / 8 + p * 32;
            int c = (tid % 8) * 4;
            float4 v = *reinterpret_cast<const float4*>(&A[(m0 + r) * DIM + k0 + c]);
            As[c + 0][r] = v.x; As[c + 1][r] = v.y;
            As[c + 2][r] = v.z; As[c + 3][r] = v.w;
        }
        #pragma unroll
        for (int p = 0; p < 2; p++) {
            int r = tid / 16 + p * 16;
            int c = (tid % 16) * 4;
            *reinterpret_cast<float4*>(&Bs[r][c]) =
                *reinterpret_cast<const float4*>(&W[(k0 + r) * DIM + e0 + c]);
        }
        __syncthreads();

        #pragma unroll
        for (int kk = 0; kk < PBK; kk++) {
            float4 av4 = *reinterpret_cast<const float4*>(&As[kk][ty * 4]);
            float4 bv4 = *reinterpret_cast<const float4*>(&Bs[kk][tx * 4]);
            float av[4] = {av4.x, av4.y, av4.z, av4.w};
            float bv[4] = {bv4.x, bv4.y, bv4.z, bv4.w};
            #pragma unroll
            for (int i = 0; i < 4; i++)
                #pragma unroll
                for (int j = 0; j < 4; j++)
                    acc[i][j] = fmaf(av[i], bv[j], acc[i][j]);
        }
        __syncthreads();
    }

    // transposed epilogue: C[e][m], 4 consecutive m per store
    #pragma unroll
    for (int j = 0; j < 4; j++) {
        const int e = e0 + tx * 4 + j;
        float4 v = make_float4(acc[0][j], acc[1][j], acc[2][j], acc[3][j]);
        if (!which) {
            const float bb = b1[e];
            v.x += bb; v.y += bb; v.z += bb; v.w += bb;
        }
        *reinterpret_cast<float4*>(&C[e * MROWS + m0 + ty * 4]) = v;
    }
}

// ---------------------------------------------------------------------------
// Kernel 2: fused cross + gelu + reduction over d, packed f32x2 math.
//   out[b][n][m] = sum_d gelu(xp[b,n,d] + yp[b,m,d]) * W2[d] + b2
// 32(n) x 32(m) tile, 64 threads, 4x4 outputs/thread, d chunked at 64,
// d-major smem tiles (coalesced producer, conflict-free STS/LDS).
// ---------------------------------------------------------------------------
#define TBN 32
#define TBM 32
#define DK  64
#define SPAD 36   // row stride (floats): 16B-aligned, conflict-free

__global__ __launch_bounds__(64)
void cross_kernel(const float* __restrict__ W2,
                  const float* __restrict__ b2,
                  float* __restrict__ out)
{
    __shared__ float sx[DK][SPAD];   // [d][n]
    __shared__ float sy[DK][SPAD];   // [d][m]
    __shared__ float sw[DK];

    const int b  = blockIdx.z;
    const int n0 = blockIdx.x * TBN;
    const int m0 = blockIdx.y * TBM;
    const int tid = threadIdx.x;          // 0..63
    const int tx = tid % 8;               // m group: 4 outputs
    const int ty = tid / 8;               // n group: 4 outputs

    const int bx = b * NN1 + n0;          // column base into g_xp_t
    const int by = b * NN2 + m0;          // column base into g_yp_t

    const unsigned long long C0   = pk2(0.7978845608f, 0.7978845608f);
    const unsigned long long C1   = pk2(0.0356774081f, 0.0356774081f);

    unsigned long long acc[4][2];
    #pragma unroll
    for (int i = 0; i < 4; i++) { acc[i][0] = 0ull; acc[i][1] = 0ull; }

    for (int d0 = 0; d0 < DIM; d0 += DK) {
        // producer: copy [DK][32] tiles of xp^T / yp^T (coalesced gmem reads)
        #pragma unroll
        for (int it = 0; it < 8; it++) {
            const int q  = it * 64 + tid;
            const int dd = q >> 3;            // 0..63
            const int c4 = (q & 7) * 4;       // 0..28
            *reinterpret_cast<float4*>(&sx[dd][c4]) =
                *reinterpret_cast<const float4*>(&g_xp_t[(d0 + dd) * MROWS + bx + c4]);
            *reinterpret_cast<float4*>(&sy[dd][c4]) =
                *reinterpret_cast<const float4*>(&g_yp_t[(d0 + dd) * MROWS + by + c4]);
        }
        sw[tid] = W2[d0 + tid];
        __syncthreads();

        #pragma unroll 2
        for (int d = 0; d < DK; d++) {
            const float w2s = sw[d];
            const unsigned long long w2p = pk2(w2s, w2s);
            const float4 a4 = *reinterpret_cast<const float4*>(&sx[d][ty * 4]);
            const float4 b4 = *reinterpret_cast<const float4*>(&sy[d][tx * 4]);

            unsigned long long adup[4];
            adup[0] = pk2(a4.x, a4.x); adup[1] = pk2(a4.y, a4.y);
            adup[2] = pk2(a4.z, a4.z); adup[3] = pk2(a4.w, a4.w);
            unsigned long long bp[2];
            bp[0] = pk2(b4.x, b4.y);   bp[1] = pk2(b4.z, b4.w);

            #pragma unroll
            for (int i = 0; i < 4; i++) {
                #pragma unroll
                for (int jp = 0; jp < 2; jp++) {
                    unsigned long long h  = f2add(adup[i], bp[jp]);
                    unsigned long long x2 = f2mul(h, h);
                    unsigned long long pp = f2fma(C1, x2, C0);
                    unsigned long long t  = f2mul(h, pp);
                    float t0, t1; upk2(t0, t1, t);
                    unsigned long long thp = pk2(tanhf_hw(t0), tanhf_hw(t1));
                    unsigned long long hh  = f2mul(h, 0x3F0000003F000000ull); // (0.5,0.5)
                    unsigned long long g   = f2fma(hh, thp, hh);
                    acc[i][jp] = f2fma(g, w2p, acc[i][jp]);
                }
            }
        }
        __syncthreads();
    }

    const float bias = b2[0];
    #pragma unroll
    for (int i = 0; i < 4; i++) {
        const int n = n0 + ty * 4 + i;
        float o0, o1, o2, o3;
        upk2(o0, o1, acc[i][0]);
        upk2(o2, o3, acc[i][1]);
        float4 v = make_float4(o0 + bias, o1 + bias, o2 + bias, o3 + bias);
        *reinterpret_cast<float4*>(&out[(b * NN1 + n) * NN2 + m0 + tx * 4]) = v;
    }
}

// ---------------------------------------------------------------------------
extern "C" void kernel_launch(void* const* d_in, const int* in_sizes, int n_in,
                              void* d_out, int out_size)
{
    const float* x  = (const float*)d_in[0];   // (4, 512, 256)
    const float* y  = (const float*)d_in[1];   // (4, 512, 256)
    const float* W1 = (const float*)d_in[2];   // (512, 256)
    const float* b1 = (const float*)d_in[3];   // (256,)
    const float* W2 = (const float*)d_in[4];   // (256, 1)
    const float* b2 = (const float*)d_in[5];   // (1,)
    float* out = (float*)d_out;                // (4, 512, 512)

    (void)in_sizes; (void)n_in; (void)out_size;

    dim3 pgrid(MROWS / PBM, DIM / PBN, 2);
    proj_kernel<<<pgrid, 256>>>(x, y, W1, b1);

    dim3 cgrid(NN1 / TBN, NN2 / TBM, BATCH);
    cross_kernel<<<cgrid, 64>>>(W2, b2, out);
}